// round 4
// baseline (speedup 1.0000x reference)
#include <cuda_runtime.h>
#include <cstdint>

// ---------------- problem constants ----------------
#define FMDIM   32
#define NPOS    1024            // 32*32
#define NANCH   9216            // 1024*9
#define NSORT   16384           // next pow2
#define NWORDS  144             // 9216/64
#define IOU_THR 0.7f
#define TOPK    300

// ---------------- scratch (static __device__, allocation-free) ----------------
__device__ float  g_col1[768 * 1024];          // im2col for backbone conv (3 MB)
__device__ float  g_feat[512 * 1024];          // backbone features          (2 MB)
__device__ float  g_col2[4608 * 1024];         // im2col for rpn conv       (18 MB)
__device__ float  g_hid [512 * 1024];          // rpn hidden                 (2 MB)
__device__ float  g_head[45 * 1024];           // rows 0..8 = cls ch 9..17, rows 9..44 = box ch 0..35
__device__ float4 g_prop[NANCH];               // decoded proposals
__device__ unsigned long long g_keys[NSORT];   // sort keys
__device__ float4 g_boxes[NANCH];              // sorted boxes
__device__ unsigned long long g_mask[(size_t)NANCH * NWORDS]; // NMS bitmask (10.6 MB)

// ---------------- im2col for backbone (16x16 stride16 VALID) ----------------
__global__ void im2col1_k(const float* __restrict__ img)
{
    int idx = blockIdx.x * blockDim.x + threadIdx.x;   // 768*1024 threads
    int k = idx >> 10, p = idx & 1023;
    int ci = k >> 8, r = k & 255, ky = r >> 4, kx = r & 15;
    int py = p >> 5, px = p & 31;
    g_col1[idx] = img[ci * 512 * 512 + (py * 16 + ky) * 512 + (px * 16 + kx)];
}

// ---------------- im2col for rpn 3x3 SAME ----------------
__global__ void im2col2_k()
{
    int idx = blockIdx.x * blockDim.x + threadIdx.x;   // 4608*1024 threads
    int k = idx >> 10, p = idx & 1023;
    int ci = k / 9, r = k - ci * 9, dy = r / 3, dx = r - dy * 3;
    int py = p >> 5, px = p & 31;
    int y = py + dy - 1, x = px + dx - 1;
    float v = 0.0f;
    if ((unsigned)y < 32u && (unsigned)x < 32u) v = g_feat[ci * 1024 + y * 32 + x];
    g_col2[idx] = v;
}

// ---------------- FP32 GEMM: C[M][1024] = A[M][K] * B[K][1024] (+bias, relu) ----------------
// 64x64 block tile, BK=16, 256 threads, 4x4 per thread, software-pipelined global loads.
__global__ void gemm_k(const float* __restrict__ A, const float* __restrict__ B,
                       float* __restrict__ C, int M, int K,
                       const float* __restrict__ bias, int relu)
{
    __shared__ float As[16][68];   // [k][m], padded to dodge store conflicts
    __shared__ float Bs[16][64];   // [k][n]

    const int bn  = blockIdx.x * 64;
    const int bm  = blockIdx.y * 64;
    const int tid = threadIdx.x;
    const int tx  = tid & 15, ty = tid >> 4;
    const int lm  = tid >> 2, lkq = (tid & 3) * 4;     // A loader: m row, k quad
    const int lkb = tid >> 4, ln4 = (tid & 15) * 4;    // B loader: k row, n quad

    float acc[4][4] = {};

    // prologue loads
    float4 av = make_float4(0.f, 0.f, 0.f, 0.f);
    if (bm + lm < M) av = *(const float4*)(A + (size_t)(bm + lm) * K + lkq);
    float4 bv = *(const float4*)(B + (size_t)lkb * 1024 + bn + ln4);

    for (int k0 = 0; k0 < K; k0 += 16) {
        As[lkq + 0][lm] = av.x; As[lkq + 1][lm] = av.y;
        As[lkq + 2][lm] = av.z; As[lkq + 3][lm] = av.w;
        *(float4*)&Bs[lkb][ln4] = bv;
        __syncthreads();

        int kn = k0 + 16;
        if (kn < K) {                                  // prefetch next tile
            av = make_float4(0.f, 0.f, 0.f, 0.f);
            if (bm + lm < M) av = *(const float4*)(A + (size_t)(bm + lm) * K + kn + lkq);
            bv = *(const float4*)(B + (size_t)(kn + lkb) * 1024 + bn + ln4);
        }

#pragma unroll
        for (int k = 0; k < 16; k++) {
            float4 a = *(const float4*)&As[k][ty * 4];
            float4 b = *(const float4*)&Bs[k][tx * 4];
            acc[0][0] += a.x * b.x; acc[0][1] += a.x * b.y; acc[0][2] += a.x * b.z; acc[0][3] += a.x * b.w;
            acc[1][0] += a.y * b.x; acc[1][1] += a.y * b.y; acc[1][2] += a.y * b.z; acc[1][3] += a.y * b.w;
            acc[2][0] += a.z * b.x; acc[2][1] += a.z * b.y; acc[2][2] += a.z * b.z; acc[2][3] += a.z * b.w;
            acc[3][0] += a.w * b.x; acc[3][1] += a.w * b.y; acc[3][2] += a.w * b.z; acc[3][3] += a.w * b.w;
        }
        __syncthreads();
    }

#pragma unroll
    for (int r = 0; r < 4; r++) {
        int m = bm + ty * 4 + r;
        if (m < M) {
            float bb = bias[m];
            float4 o = make_float4(acc[r][0] + bb, acc[r][1] + bb, acc[r][2] + bb, acc[r][3] + bb);
            if (relu) {
                o.x = fmaxf(o.x, 0.f); o.y = fmaxf(o.y, 0.f);
                o.z = fmaxf(o.z, 0.f); o.w = fmaxf(o.w, 0.f);
            }
            *(float4*)(C + (size_t)m * 1024 + bn + tx * 4) = o;
        }
    }
}

// ---------------- decode proposals + build sort keys ----------------
__global__ void decode_k(const float* __restrict__ anchors)
{
    int i = blockIdx.x * blockDim.x + threadIdx.x;     // 16384 threads
    if (i >= NANCH) { if (i < NSORT) g_keys[i] = ~0ull; return; }

    int p = i / 9, k = i - p * 9;
    float s  = g_head[k * 1024 + p];
    float d0 = g_head[(9 + k * 4 + 0) * 1024 + p];
    float d1 = g_head[(9 + k * 4 + 1) * 1024 + p];
    float d2 = g_head[(9 + k * 4 + 2) * 1024 + p];
    float d3 = g_head[(9 + k * 4 + 3) * 1024 + p];

    const float* a = anchors + (size_t)i * 4;
    float ax1 = a[0], ay1 = a[1], ax2 = a[2], ay2 = a[3];
    float wa = ax2 - ax1, ha = ay2 - ay1;
    float cxa = ax1 + 0.5f * wa, cya = ay1 + 0.5f * ha;
    float dw = fminf(fmaxf(d2, -4.f), 4.f);
    float dh = fminf(fmaxf(d3, -4.f), 4.f);
    float cx = cxa + d0 * wa, cy = cya + d1 * ha;
    float w  = wa * expf(dw), h = ha * expf(dh);
    float x1 = fmaxf(cx - 0.5f * w, 0.f);
    float y1 = fmaxf(cy - 0.5f * h, 0.f);
    float x2 = fminf(cx + 0.5f * w, 511.f);
    float y2 = fminf(cy + 0.5f * h, 511.f);
    g_prop[i] = make_float4(x1, y1, x2, y2);

    // key: score descending (stable by index ascending)
    unsigned b   = __float_as_uint(s);
    unsigned asc = (b & 0x80000000u) ? ~b : (b | 0x80000000u);
    unsigned dsc = ~asc;
    g_keys[i] = ((unsigned long long)dsc << 32) | (unsigned)i;
}

// ---------------- single-block bitonic sort of 16384 u64 keys ----------------
__global__ void sort_k()
{
    extern __shared__ unsigned long long sk[];
    int tid = threadIdx.x;
    for (int i = tid; i < NSORT; i += 1024) sk[i] = g_keys[i];
    __syncthreads();
    for (int k = 2; k <= NSORT; k <<= 1) {
        for (int j = k >> 1; j > 0; j >>= 1) {
            for (int e = tid; e < NSORT; e += 1024) {
                int ixj = e ^ j;
                if (ixj > e) {
                    unsigned long long x = sk[e], y = sk[ixj];
                    bool up = ((e & k) == 0);
                    if (up ? (x > y) : (x < y)) { sk[e] = y; sk[ixj] = x; }
                }
            }
            __syncthreads();
        }
    }
    for (int i = tid; i < NSORT; i += 1024) g_keys[i] = sk[i];
}

// ---------------- gather sorted boxes ----------------
__global__ void gather_k()
{
    int i = blockIdx.x * blockDim.x + threadIdx.x;     // 9216 threads
    if (i < NANCH) {
        int idx = (int)(g_keys[i] & 0xFFFFFFFFull);
        g_boxes[i] = g_prop[idx];
    }
}

// ---------------- NMS bitmask: mask[i][jb] bit jj set iff j>i and IoU>thr ----------------
__global__ void nms_mask_k()
{
    __shared__ float4 cb[64];
    int bxb = blockIdx.x, byb = blockIdx.y;
    int t = threadIdx.x;
    cb[t] = g_boxes[bxb * 64 + t];
    __syncthreads();

    int i = byb * 64 + t;
    unsigned long long m = 0ull;
    if (bxb >= byb) {
        float4 b  = g_boxes[i];
        float  ai = (b.z - b.x) * (b.w - b.y);
#pragma unroll 4
        for (int jj = 0; jj < 64; jj++) {
            int j = bxb * 64 + jj;
            if (j > i) {
                float4 c  = cb[jj];
                float  aj = (c.z - c.x) * (c.w - c.y);
                float iw = fmaxf(fminf(b.z, c.z) - fmaxf(b.x, c.x), 0.f);
                float ih = fmaxf(fminf(b.w, c.w) - fmaxf(b.y, c.y), 0.f);
                float inter = iw * ih;
                float iou = inter / (ai + aj - inter + 1e-9f);
                if (iou > IOU_THR) m |= (1ull << jj);
            }
        }
    }
    g_mask[(size_t)i * NWORDS + bxb] = m;
}

// ---------------- serial greedy reduce (exact reference semantics), early exit at 300 kept ----------------
__global__ void nms_reduce_k(float* __restrict__ out)
{
    __shared__ unsigned long long remv[NWORDS];
    __shared__ unsigned long long keepw[NWORDS];
    __shared__ int sel[TOPK];
    __shared__ int s_cnt, s_flag, s_done;

    int t = threadIdx.x;
    if (t < NWORDS) { remv[t] = 0ull; keepw[t] = 0ull; }
    if (t == 0) { s_cnt = 0; s_done = 0; }
    __syncthreads();

    for (int i = 0; i < NANCH; i++) {
        if (t == 0) {
            bool rm = (remv[i >> 6] >> (i & 63)) & 1ull;
            int f = 0;
            if (!rm) {
                sel[s_cnt] = i;
                s_cnt++;
                keepw[i >> 6] |= (1ull << (i & 63));
                if (s_cnt >= TOPK) s_done = 1; else f = 1;
            }
            s_flag = f;
        }
        __syncthreads();
        if (s_done) break;                       // uniform: all threads see it
        if (s_flag && t < NWORDS)
            remv[t] |= g_mask[(size_t)i * NWORDS + t];
        __syncthreads();
    }
    __syncthreads();

    // if fewer than 300 kept: stable argsort(~keep) appends suppressed in order
    if (t == 0 && s_cnt < TOPK) {
        for (int i = 0; i < NANCH && s_cnt < TOPK; i++)
            if (!((keepw[i >> 6] >> (i & 63)) & 1ull)) sel[s_cnt++] = i;
    }
    __syncthreads();

    for (int s = t; s < TOPK; s += blockDim.x) {
        float4 b = g_boxes[sel[s]];
        out[s * 4 + 0] = b.x; out[s * 4 + 1] = b.y;
        out[s * 4 + 2] = b.z; out[s * 4 + 3] = b.w;
    }
}

// ---------------- launch ----------------
extern "C" void kernel_launch(void* const* d_in, const int* in_sizes, int n_in,
                              void* d_out, int out_size)
{
    const float* img     = (const float*)d_in[0];
    const float* anchors = (const float*)d_in[1];
    const float* w_bb    = (const float*)d_in[2];
    const float* b_bb    = (const float*)d_in[3];
    const float* w_rpn   = (const float*)d_in[4];
    const float* b_rpn   = (const float*)d_in[5];
    const float* w_cls   = (const float*)d_in[6];
    const float* b_cls   = (const float*)d_in[7];
    const float* w_box   = (const float*)d_in[8];
    const float* b_box   = (const float*)d_in[9];
    float* out = (float*)d_out;

    float *col1, *feat, *col2, *hid, *head;
    cudaGetSymbolAddress((void**)&col1, g_col1);
    cudaGetSymbolAddress((void**)&feat, g_feat);
    cudaGetSymbolAddress((void**)&col2, g_col2);
    cudaGetSymbolAddress((void**)&hid,  g_hid);
    cudaGetSymbolAddress((void**)&head, g_head);

    // backbone conv: feat[512][1024] = w_bb[512][768] x col1[768][1024], relu
    im2col1_k<<<3072, 256>>>(img);
    gemm_k<<<dim3(16, 8), 256>>>(w_bb, col1, feat, 512, 768, b_bb, 1);

    // rpn conv: hid[512][1024] = w_rpn[512][4608] x col2[4608][1024], relu
    im2col2_k<<<18432, 256>>>();
    gemm_k<<<dim3(16, 8), 256>>>(w_rpn, col2, hid, 512, 4608, b_rpn, 1);

    // heads (1x1 convs): B = hid directly
    gemm_k<<<dim3(16, 1), 256>>>(w_cls + 9 * 512, hid, head,            9,  512, b_cls + 9, 0);
    gemm_k<<<dim3(16, 1), 256>>>(w_box,           hid, head + 9 * 1024, 36, 512, b_box,     0);

    // decode + keys, sort, gather
    decode_k<<<64, 256>>>(anchors);
    cudaFuncSetAttribute(sort_k, cudaFuncAttributeMaxDynamicSharedMemorySize, 131072);
    sort_k<<<1, 1024, 131072>>>();
    gather_k<<<36, 256>>>();

    // NMS
    nms_mask_k<<<dim3(NWORDS, NWORDS), 64>>>();
    nms_reduce_k<<<1, 256>>>(out);
}